// round 11
// baseline (speedup 1.0000x reference)
#include <cuda_runtime.h>
#include <cuda_bf16.h>
#include <math.h>
#include <stdint.h>

#define B_  4
#define T_  2305
#define C_  384
#define H_  6
#define BH_ (B_*H_)          // 24
#define DH  64
#define HW  48
#define M_  (B_*T_)          // 9220 rows
#define BN_EPS 1e-5f
#define NKT 37               // key tiles of 64
#define KT  (NKT*64)         // 2368 padded keys
#define QPAD 2432            // 19*128 padded queries

// Interleaved fragment layout in GLOBAL K/V arrays:
// per 64-u32 row, fragment {hi(p), hi(p+4), lo(p), lo(p+4)} at slots (ks*4+tig)*4..+3
__device__ __forceinline__ int pslot(int p)   // returns hi slot (pair lo = +2)
{
    int t8 = p & 7;
    return (((p >> 3) * 4 + (t8 & 3)) << 2) + (t8 >> 2);
}

// GEMM smem swizzle: uint4-slot s (0..7) xor'd with row bits; conflict-free for
// both STS.128 stores and LDS.128 fragment loads (bank-enumerated).
#define SW(s,row) ((s) ^ ((((row)&1)<<2) ^ ((row)&3)))

// ---------------- device scratch (256B-aligned) ----------------
__device__ __align__(256) float g_qin[M_*C_];
__device__ __align__(256) float g_kin[M_*C_];
__device__ __align__(256) float g_vin[M_*C_];
__device__ __align__(256) float g_q  [M_*C_];            // (b,h,t,d) fp32
__device__ __align__(256) float g_v  [M_*C_];            // (b,h,t,d) fp32
__device__ __align__(256) uint32_t g_kp[BH_*KT*64];      // (b,h)[t][64] interleaved frags
__device__ __align__(256) uint32_t g_vt[BH_*DH*NKT*64];  // (b,h)[d][tile][64] interleaved
__device__ __align__(256) float g_po [BH_*3*QPAD*64];    // attention partial O
__device__ __align__(256) float g_pml[BH_*3*QPAD*2];     // attention partial (m,l)

// ---------------- bf16 mma m16n8k16 + helpers ----------------
__device__ __forceinline__ void mma_bf16(float c[4], const uint32_t a[4],
                                         uint32_t b0, uint32_t b1)
{
    asm volatile(
        "mma.sync.aligned.m16n8k16.row.col.f32.bf16.bf16.f32 "
        "{%0,%1,%2,%3}, {%4,%5,%6,%7}, {%8,%9}, {%0,%1,%2,%3};\n"
        : "+f"(c[0]), "+f"(c[1]), "+f"(c[2]), "+f"(c[3])
        : "r"(a[0]), "r"(a[1]), "r"(a[2]), "r"(a[3]), "r"(b0), "r"(b1));
}

__device__ __forceinline__ void split_pack(float x, float y, uint32_t& hi, uint32_t& lo)
{
    __nv_bfloat162 h = __floats2bfloat162_rn(x, y);
    float xr = x - __bfloat162float(h.x);
    float yr = y - __bfloat162float(h.y);
    __nv_bfloat162 l = __floats2bfloat162_rn(xr, yr);
    hi = *reinterpret_cast<uint32_t*>(&h);
    lo = *reinterpret_cast<uint32_t*>(&l);
}

// hi-only pack (P in PV: 2-term)
__device__ __forceinline__ uint32_t pack_hi(float x, float y)
{
    __nv_bfloat162 h = __floats2bfloat162_rn(x, y);
    return *reinterpret_cast<uint32_t*>(&h);
}

__device__ __forceinline__ float ex2(float x)
{
    float y;
    asm("ex2.approx.ftz.f32 %0, %1;" : "=f"(y) : "f"(x));
    return y;
}

// ---------------- kernel 1: depthwise conv 3x3 + BN ----------------
__global__ void prep_kernel(const float* __restrict__ x,
    const float* __restrict__ kq, const float* __restrict__ kk,
    const float* __restrict__ kv,
    const float* __restrict__ gq, const float* __restrict__ bq,
    const float* __restrict__ mq, const float* __restrict__ vq,
    const float* __restrict__ gk, const float* __restrict__ bk,
    const float* __restrict__ mk, const float* __restrict__ vk,
    const float* __restrict__ gv, const float* __restrict__ bv,
    const float* __restrict__ mv, const float* __restrict__ vv)
{
    int idx = blockIdx.x*blockDim.x + threadIdx.x;
    if (idx >= M_*C_) return;
    int c = idx % C_;
    int t = (idx / C_) % T_;
    int b = idx / (C_*T_);
    const float* xb = x + (size_t)b*T_*C_;
    if (t == 0) {
        float v = xb[c];
        g_qin[idx] = v; g_kin[idx] = v; g_vin[idx] = v;
        return;
    }
    int p = t - 1, py = p / HW, px = p % HW;
    float aq = 0.f, ak = 0.f, av = 0.f;
    #pragma unroll
    for (int dy = 0; dy < 3; dy++) {
        int ny = py + dy - 1;
        if ((unsigned)ny >= (unsigned)HW) continue;
        #pragma unroll
        for (int dx = 0; dx < 3; dx++) {
            int nx = px + dx - 1;
            if ((unsigned)nx >= (unsigned)HW) continue;
            float xv = xb[(size_t)(1 + ny*HW + nx)*C_ + c];
            int tap = dy*3 + dx;
            aq = fmaf(xv, kq[c*9 + tap], aq);
            ak = fmaf(xv, kk[c*9 + tap], ak);
            av = fmaf(xv, kv[c*9 + tap], av);
        }
    }
    g_qin[idx] = (aq - mq[c]) * (gq[c]*rsqrtf(vq[c]+BN_EPS)) + bq[c];
    g_kin[idx] = (ak - mk[c]) * (gk[c]*rsqrtf(vk[c]+BN_EPS)) + bk[c];
    g_vin[idx] = (av - mv[c]) * (gv[c]*rsqrtf(vv[c]+BN_EPS)) + bv[c];
}

// ============ GEMM building blocks (interleaved + swizzled, DOUBLE-BUFFERED) ====
// BM=128, BN=64, BK=32, 256 threads. 48 KB dynamic smem: sA 2x[128x32u32], sW 2x[64x32u32].
#define GEMM_SMEM_DECL \
    extern __shared__ __align__(16) uint32_t gsm[]; \
    uint4* sA4 = reinterpret_cast<uint4*>(gsm); \
    uint4* sW4 = reinterpret_cast<uint4*>(gsm + 2*128*32);

#define GEMM_STORE_A(buf) \
    _Pragma("unroll") \
    for (int tg = 0; tg < 4; tg++) { \
        float x0, x1, y0, y1; \
        if (tg & 1) { x0 = ra[tg>>1].z; x1 = ra[tg>>1].w; \
                      y0 = ra[2+(tg>>1)].z; y1 = ra[2+(tg>>1)].w; } \
        else        { x0 = ra[tg>>1].x; x1 = ra[tg>>1].y; \
                      y0 = ra[2+(tg>>1)].x; y1 = ra[2+(tg>>1)].y; } \
        uint32_t hA, lA, hB, lB; \
        split_pack(x0, x1, hA, lA); \
        split_pack(y0, y1, hB, lB); \
        sA4[(buf)*1024 + arow*8 + SW(aks*4 + tg, arow)] = make_uint4(hA, hB, lA, lB); \
    }

#define GEMM_STORE_W(buf) \
    _Pragma("unroll") \
    for (int j = 0; j < 2; j++) { \
        float x0 = j ? rw0.z : rw0.x, x1 = j ? rw0.w : rw0.y; \
        float y0 = j ? rw1.z : rw1.x, y1 = j ? rw1.w : rw1.y; \
        uint32_t hA, lA, hB, lB; \
        split_pack(x0, x1, hA, lA); \
        split_pack(y0, y1, hB, lB); \
        int tg = 2*wq + j; \
        sW4[(buf)*512 + wrow*8 + SW(wks*4 + tg, wrow)] = make_uint4(hA, hB, lA, lB); \
    }

#define GEMM_MMA_BLOCK(buf) \
    _Pragma("unroll") \
    for (int ks = 0; ks < 2; ks++) { \
        int fs = ks*4 + tig; \
        uint4 a0 = sA4[(buf)*1024 + (w*16+gid  )*8 + SW(fs, gid)]; \
        uint4 a1 = sA4[(buf)*1024 + (w*16+gid+8)*8 + SW(fs, gid)]; \
        uint32_t ah[4] = {a0.x, a1.x, a0.y, a1.y}; \
        uint32_t al[4] = {a0.z, a1.z, a0.w, a1.w}; \
        _Pragma("unroll") \
        for (int ng = 0; ng < 2; ng++) { \
            uint4 u[4]; \
            _Pragma("unroll") \
            for (int j = 0; j < 4; j++) \
                u[j] = sW4[(buf)*512 + ((ng*4+j)*8+gid)*8 + SW(fs, gid)]; \
            _Pragma("unroll") \
            for (int j = 0; j < 4; j++) mma_bf16(acc[ng*4+j], ah, u[j].x, u[j].y); \
            _Pragma("unroll") \
            for (int j = 0; j < 4; j++) mma_bf16(acc[ng*4+j], ah, u[j].z, u[j].w); \
            _Pragma("unroll") \
            for (int j = 0; j < 4; j++) mma_bf16(acc[ng*4+j], al, u[j].x, u[j].y); \
        } \
    }

#define GEMM_LOAD_W(k0off) \
    rw0 = *(const float4*)(W + (size_t)(n0 + wrow)*C_ + (k0off) + wks*16 + wq*4); \
    rw1 = *(const float4*)(W + (size_t)(n0 + wrow)*C_ + (k0off) + wks*16 + wq*4 + 8);

#define GEMM_SMEM_BYTES ((2*128*32 + 2*64*32)*4)   // 49152

// ---------------- fused QKV GEMM (double-buffered) ----------------
__global__ void __launch_bounds__(256) gemm_qkv(
    const float* __restrict__ Aq, const float* __restrict__ Ak, const float* __restrict__ Av,
    const float* __restrict__ Wq, const float* __restrict__ Wk, const float* __restrict__ Wv,
    float* __restrict__ Dq, float* __restrict__ Dv, uint32_t* __restrict__ Kp)
{
    GEMM_SMEM_DECL
    int z = blockIdx.z;
    const float* A = (z==0) ? Aq : (z==1) ? Ak : Av;
    const float* W = (z==0) ? Wq : (z==1) ? Wk : Wv;
    int m0 = blockIdx.x*128, n0 = blockIdx.y*64;
    int tid = threadIdx.x, w = tid>>5, lane = tid&31;
    int gid = lane>>2, tig = lane&3;
    float acc[8][4] = {};
    int arow = tid>>1, aks = tid&1;
    int wrow = tid>>2, wks = (tid>>1)&1, wq = tid&1;
    int gm = m0 + arow;

    float4 ra[4], rw0, rw1;
    #define QKV_LOAD_A(k0off) \
        _Pragma("unroll") \
        for (int i = 0; i < 4; i++) \
            ra[i] = (gm < M_) ? *(const float4*)(A + (size_t)gm*C_ + (k0off) + aks*16 + i*4) \
                              : make_float4(0.f,0.f,0.f,0.f);

    // prologue: fill buf0 with k=0, prefetch k=32
    QKV_LOAD_A(0)
    GEMM_LOAD_W(0)
    GEMM_STORE_A(0)
    GEMM_STORE_W(0)
    QKV_LOAD_A(32)
    GEMM_LOAD_W(32)
    __syncthreads();

    int cur = 0;
    for (int k0 = 0; k0 < C_; k0 += 32) {
        if (k0 + 32 < C_) {
            GEMM_STORE_A(cur^1)
            GEMM_STORE_W(cur^1)
            if (k0 + 64 < C_) {
                QKV_LOAD_A(k0+64)
                GEMM_LOAD_W(k0+64)
            }
        }
        GEMM_MMA_BLOCK(cur)
        __syncthreads();
        cur ^= 1;
    }
    #undef QKV_LOAD_A

    #pragma unroll
    for (int nt = 0; nt < 8; nt++) {
        int gn = n0 + nt*8 + 2*tig;
        #pragma unroll
        for (int half = 0; half < 2; half++) {
            int gmo = m0 + w*16 + gid + half*8;
            if (gmo >= M_) continue;
            float v0 = acc[nt][half*2+0], v1 = acc[nt][half*2+1];
            int b = gmo / T_, t = gmo % T_;
            int h = gn >> 6, d = gn & 63;
            if (z == 1) {
                uint32_t hi, lo;
                split_pack(v0, v1, hi, lo);
                size_t base = ((size_t)(b*H_ + h)*KT + t)*64;
                int s0 = pslot(d >> 1);
                Kp[base + s0] = hi; Kp[base + s0 + 2] = lo;
            } else {
                float* D = (z==0) ? Dq : Dv;
                float* p = &D[(((size_t)b*H_ + h)*T_ + t)*DH + d];
                p[0] = v0; p[1] = v1;
            }
        }
    }
}

// ---------------- output GEMM (double-buffered; merge of KV-split fused into A load) ----
__global__ void __launch_bounds__(256) gemm_o(
    const float* __restrict__ po, const float* __restrict__ pml,
    const float* __restrict__ W,
    const float* __restrict__ bias, float* __restrict__ D)
{
    GEMM_SMEM_DECL
    int m0 = blockIdx.x*128, n0 = blockIdx.y*64;
    int tid = threadIdx.x, w = tid>>5, lane = tid&31;
    int gid = lane>>2, tig = lane&3;
    float acc[8][4] = {};
    int arow = tid>>1, aks = tid&1;
    int wrow = tid>>2, wks = (tid>>1)&1, wq = tid&1;
    int gm = m0 + arow;
    int bO = gm / T_, tO = gm % T_;      // valid only when gm < M_

    float4 ra[4], rw0, rw1;
    // merged A load: A[gm][kc..kc+15] = sum_z w_z * po_z, normalized
    #define O_LOAD_A(k0off) \
    { \
        if (gm < M_) { \
            int kc = (k0off) + aks*16; \
            int h = kc >> 6, d0 = kc & 63; \
            size_t pb = (size_t)(bO*H_ + h)*3*QPAD; \
            float2 ml0 = *(const float2*)&pml[(pb            + tO)*2]; \
            float2 ml1 = *(const float2*)&pml[(pb +   QPAD   + tO)*2]; \
            float2 ml2 = *(const float2*)&pml[(pb + 2*QPAD   + tO)*2]; \
            float Mx = fmaxf(ml0.x, fmaxf(ml1.x, ml2.x)); \
            float w0 = ex2(ml0.x - Mx), w1 = ex2(ml1.x - Mx), w2 = ex2(ml2.x - Mx); \
            float invL = 1.0f / (ml0.y*w0 + ml1.y*w1 + ml2.y*w2); \
            w0 *= invL; w1 *= invL; w2 *= invL; \
            const float* p0 = &po[(pb            + tO)*64 + d0]; \
            const float* p1 = &po[(pb +   QPAD   + tO)*64 + d0]; \
            const float* p2 = &po[(pb + 2*QPAD   + tO)*64 + d0]; \
            _Pragma("unroll") \
            for (int i = 0; i < 4; i++) { \
                float4 a0 = *(const float4*)(p0 + i*4); \
                float4 a1 = *(const float4*)(p1 + i*4); \
                float4 a2 = *(const float4*)(p2 + i*4); \
                ra[i] = make_float4(a0.x*w0 + a1.x*w1 + a2.x*w2, \
                                    a0.y*w0 + a1.y*w1 + a2.y*w2, \
                                    a0.z*w0 + a1.z*w1 + a2.z*w2, \
                                    a0.w*w0 + a1.w*w1 + a2.w*w2); \
            } \
        } else { \
            _Pragma("unroll") \
            for (int i = 0; i < 4; i++) ra[i] = make_float4(0.f,0.f,0.f,0.f); \
        } \
    }

    // prologue
    O_LOAD_A(0)
    GEMM_LOAD_W(0)
    GEMM_STORE_A(0)
    GEMM_STORE_W(0)
    O_LOAD_A(32)
    GEMM_LOAD_W(32)
    __syncthreads();

    int cur = 0;
    for (int k0 = 0; k0 < C_; k0 += 32) {
        if (k0 + 32 < C_) {
            GEMM_STORE_A(cur^1)
            GEMM_STORE_W(cur^1)
            if (k0 + 64 < C_) {
                O_LOAD_A(k0+64)
                GEMM_LOAD_W(k0+64)
            }
        }
        GEMM_MMA_BLOCK(cur)
        __syncthreads();
        cur ^= 1;
    }
    #undef O_LOAD_A

    #pragma unroll
    for (int nt = 0; nt < 8; nt++) {
        int gn = n0 + nt*8 + 2*tig;
        #pragma unroll
        for (int half = 0; half < 2; half++) {
            int gmo = m0 + w*16 + gid + half*8;
            if (gmo >= M_) continue;
            float* p = &D[(size_t)gmo*C_ + gn];
            p[0] = acc[nt][half*2+0] + bias[gn];
            p[1] = acc[nt][half*2+1] + bias[gn+1];
        }
    }
}

// ---------------- V transpose + interleaved pack ----------------
__global__ void __launch_bounds__(256) vpack(const float* __restrict__ V,
                                             uint32_t* __restrict__ Vt)
{
    __shared__ float tile[64][36];
    int bh = blockIdx.z, db = blockIdx.y*32, tileidx = blockIdx.x;
    int t0 = tileidx*64;
    int tid = threadIdx.x;
    {
        int tr = tid >> 2;
        int dc = (tid & 3) * 8;
        int gt = t0 + tr;
        if (gt < T_) {
            const float* src = V + ((size_t)bh*T_ + gt)*DH + db + dc;
            *(float4*)&tile[tr][dc]   = *(const float4*)src;
            *(float4*)&tile[tr][dc+4] = *(const float4*)(src + 4);
        } else {
            float4 z = make_float4(0.f,0.f,0.f,0.f);
            *(float4*)&tile[tr][dc]   = z;
            *(float4*)&tile[tr][dc+4] = z;
        }
    }
    __syncthreads();
    {
        int d = tid >> 3;
        int tpc = (tid & 7) * 4;
        size_t base = ((size_t)(bh*DH + db + d)*NKT + tileidx)*64;
        #pragma unroll
        for (int i = 0; i < 4; i++) {
            int p = tpc + i;
            uint32_t hi, lo;
            split_pack(tile[2*p][d], tile[2*p+1][d], hi, lo);
            int s0 = pslot(p);
            Vt[base + s0] = hi; Vt[base + s0 + 2] = lo;
        }
    }
}

// ---------------- flash attention: KV-split x3, partial outputs ----------------
#define QB 128
#define ASTR 80                  // smem row stride u32 (ASTR%32==16 -> LDS.128 conflict-free)
#define KREG (64*ASTR)           // 5120 u32 per K region
#define BUFU (2*KREG)            // 10240 u32 per buffer (K + V)
#define ATTN_SMEM (2*BUFU*4)     // 81920 B
__global__ void __launch_bounds__(256,2) attn_tc2(
    const float* __restrict__ Qh,
    const uint32_t* __restrict__ Kp, const uint32_t* __restrict__ Vt,
    float* __restrict__ po, float* __restrict__ pml)
{
    extern __shared__ uint32_t su[];
    const float SCALE = 0.05103103630798288f * 1.4426950408889634f;  // 384^-0.5 * log2(e)
    int bh = blockIdx.y, zt = blockIdx.z;
    int ts = (zt == 0) ? 0 : (zt == 1) ? 12 : 24;
    int te = (zt == 2) ? NKT : ts + 12;
    int q0 = blockIdx.x * QB;
    int tid = threadIdx.x, w = tid>>5, lane = tid&31;
    int gid = lane>>2, tig = lane&3;
    int r0 = q0 + w*16 + gid, r1 = r0 + 8;
    const float* Q = Qh + (size_t)bh*T_*DH;

    uint32_t qfh[4][4], qfl[4][4];
    #pragma unroll
    for (int ks = 0; ks < 4; ks++) {
        int c0 = ks*16 + 2*tig;
        float2 x0 = (r0 < T_) ? *(const float2*)(Q + (size_t)r0*DH + c0    ) : make_float2(0.f,0.f);
        float2 x1 = (r1 < T_) ? *(const float2*)(Q + (size_t)r1*DH + c0    ) : make_float2(0.f,0.f);
        float2 x2 = (r0 < T_) ? *(const float2*)(Q + (size_t)r0*DH + c0 + 8) : make_float2(0.f,0.f);
        float2 x3 = (r1 < T_) ? *(const float2*)(Q + (size_t)r1*DH + c0 + 8) : make_float2(0.f,0.f);
        split_pack(x0.x*SCALE, x0.y*SCALE, qfh[ks][0], qfl[ks][0]);
        split_pack(x1.x*SCALE, x1.y*SCALE, qfh[ks][1], qfl[ks][1]);
        split_pack(x2.x*SCALE, x2.y*SCALE, qfh[ks][2], qfl[ks][2]);
        split_pack(x3.x*SCALE, x3.y*SCALE, qfh[ks][3], qfl[ks][3]);
    }

    uint32_t sb = (uint32_t)__cvta_generic_to_shared(su);
    const uint32_t* gK = Kp + (size_t)bh*KT*64;
    const uint32_t* gV = Vt + (size_t)bh*DH*NKT*64;

    auto issue_tile = [&](int tile, int buf) {
        #pragma unroll
        for (int i = 0; i < 8; i++) {
            int idx = i*256 + tid;          // 0..2047
            int arr = idx >> 10;            // 0 = K, 1 = V
            int rem = idx & 1023;
            int row = rem >> 4, c4 = (rem & 15) * 4;
            const uint32_t* g = (arr == 0)
                ? gK + ((size_t)(tile*64 + row))*64 + c4
                : gV + ((size_t)row*NKT + tile)*64 + c4;
            uint32_t dst = sb + (buf*BUFU + arr*KREG + row*ASTR + c4)*4;
            asm volatile("cp.async.cg.shared.global [%0], [%1], 16;\n" :: "r"(dst), "l"(g));
        }
        asm volatile("cp.async.commit_group;\n");
    };

    float m0v = -1e30f, m1v = -1e30f, l0 = 0.f, l1 = 0.f;
    float o[8][4] = {};

    issue_tile(ts, 0);

    for (int it = ts; it < te; it++) {
        asm volatile("cp.async.wait_group 0;\n" ::: "memory");
        __syncthreads();
        if (it + 1 < te) issue_tile(it+1, (it+1-ts)&1);

        int buf = (it - ts) & 1;
        const uint4* bK4 = reinterpret_cast<const uint4*>(su + buf*BUFU);
        const uint4* bV4 = reinterpret_cast<const uint4*>(su + buf*BUFU + KREG);

        // S = Q @ K^T  (bf16x3, grouped accumulators)
        float s[8][4] = {};
        #pragma unroll
        for (int ks = 0; ks < 4; ks++) {
            #pragma unroll
            for (int ng = 0; ng < 2; ng++) {
                uint4 u[4];
                #pragma unroll
                for (int j = 0; j < 4; j++)
                    u[j] = bK4[((ng*4+j)*8+gid)*(ASTR/4) + ks*4 + tig];
                #pragma unroll
                for (int j = 0; j < 4; j++) mma_bf16(s[ng*4+j], qfh[ks], u[j].x, u[j].y);
                #pragma unroll
                for (int j = 0; j < 4; j++) mma_bf16(s[ng*4+j], qfh[ks], u[j].z, u[j].w);
                #pragma unroll
                for (int j = 0; j < 4; j++) mma_bf16(s[ng*4+j], qfl[ks], u[j].x, u[j].y);
            }
        }

        // mask only in the final (partial) global tile
        if (it == NKT-1) {
            int j0 = it*64;
            #pragma unroll
            for (int nt = 0; nt < 8; nt++) {
                int cb = j0 + nt*8 + 2*tig;
                bool c0ok = cb < T_, c1ok = (cb+1) < T_;
                s[nt][0] = c0ok ? s[nt][0] : -1e30f;
                s[nt][1] = c1ok ? s[nt][1] : -1e30f;
                s[nt][2] = c0ok ? s[nt][2] : -1e30f;
                s[nt][3] = c1ok ? s[nt][3] : -1e30f;
            }
        }

        // online softmax (log2 domain)
        float mx0 = -1e30f, mx1 = -1e30f;
        #pragma unroll
        for (int nt = 0; nt < 8; nt++) {
            mx0 = fmaxf(mx0, fmaxf(s[nt][0], s[nt][1]));
            mx1 = fmaxf(mx1, fmaxf(s[nt][2], s[nt][3]));
        }
        mx0 = fmaxf(mx0, __shfl_xor_sync(0xffffffffu, mx0, 1));
        mx0 = fmaxf(mx0, __shfl_xor_sync(0xffffffffu, mx0, 2));
        mx1 = fmaxf(mx1, __shfl_xor_sync(0xffffffffu, mx1, 1));
        mx1 = fmaxf(mx1, __shfl_xor_sync(0xffffffffu, mx1, 2));

        float m0n = fmaxf(m0v, mx0), m1n = fmaxf(m1v, mx1);
        float a0 = ex2(m0v - m0n), a1 = ex2(m1v - m1n);
        float ps0 = 0.f, ps1 = 0.f;
        #pragma unroll
        for (int nt = 0; nt < 8; nt++) {
            s[nt][0] = ex2(s[nt][0] - m0n);
            s[nt][1] = ex2(s[nt][1] - m0n);
            s[nt][2] = ex2(s[nt][2] - m1n);
            s[nt][3] = ex2(s[nt][3] - m1n);
            ps0 += s[nt][0] + s[nt][1];
            ps1 += s[nt][2] + s[nt][3];
        }
        ps0 += __shfl_xor_sync(0xffffffffu, ps0, 1);
        ps0 += __shfl_xor_sync(0xffffffffu, ps0, 2);
        ps1 += __shfl_xor_sync(0xffffffffu, ps1, 1);
        ps1 += __shfl_xor_sync(0xffffffffu, ps1, 2);
        l0 = l0*a0 + ps0;  m0v = m0n;
        l1 = l1*a1 + ps1;  m1v = m1n;
        #pragma unroll
        for (int nt = 0; nt < 8; nt++) {
            o[nt][0] *= a0; o[nt][1] *= a0;
            o[nt][2] *= a1; o[nt][3] *= a1;
        }

        // O += P @ V  — P in bf16 hi only (2-term PV)
        #pragma unroll
        for (int ks = 0; ks < 4; ks++) {
            uint32_t ah[4];
            ah[0] = pack_hi(s[2*ks  ][0], s[2*ks  ][1]);
            ah[1] = pack_hi(s[2*ks  ][2], s[2*ks  ][3]);
            ah[2] = pack_hi(s[2*ks+1][0], s[2*ks+1][1]);
            ah[3] = pack_hi(s[2*ks+1][2], s[2*ks+1][3]);
            #pragma unroll
            for (int ng = 0; ng < 2; ng++) {
                uint4 u[4];
                #pragma unroll
                for (int j = 0; j < 4; j++)
                    u[j] = bV4[((ng*4+j)*8+gid)*(ASTR/4) + ks*4 + tig];
                #pragma unroll
                for (int j = 0; j < 4; j++) mma_bf16(o[ng*4+j], ah, u[j].x, u[j].y);
                #pragma unroll
                for (int j = 0; j < 4; j++) mma_bf16(o[ng*4+j], ah, u[j].z, u[j].w);
            }
        }
    }

    // epilogue: write UNNORMALIZED partials + (m,l)
    size_t pbase = (size_t)(bh*3 + zt) * QPAD;
    if (tig == 0) {
        if (r0 < T_) *(float2*)&pml[(pbase + r0)*2] = make_float2(m0v, l0);
        if (r1 < T_) *(float2*)&pml[(pbase + r1)*2] = make_float2(m1v, l1);
    }
    #pragma unroll
    for (int nt = 0; nt < 8; nt++) {
        int d = nt*8 + 2*tig;
        if (r0 < T_)
            *(float2*)&po[(pbase + r0)*64 + d] = make_float2(o[nt][0], o[nt][1]);
        if (r1 < T_)
            *(float2*)&po[(pbase + r1)*64 + d] = make_float2(o[nt][2], o[nt][3]);
    }
}

// ---------------- launch ----------------
extern "C" void kernel_launch(void* const* d_in, const int* in_sizes, int n_in,
                              void* d_out, int out_size)
{
    const float* x  = (const float*)d_in[0];
    const float* kq = (const float*)d_in[3];
    const float* kk = (const float*)d_in[4];
    const float* kv = (const float*)d_in[5];
    const float* gq = (const float*)d_in[6];
    const float* bq = (const float*)d_in[7];
    const float* mq = (const float*)d_in[8];
    const float* vq = (const float*)d_in[9];
    const float* gk = (const float*)d_in[10];
    const float* bk = (const float*)d_in[11];
    const float* mk = (const float*)d_in[12];
    const float* vk = (const float*)d_in[13];
    const float* gv = (const float*)d_in[14];
    const float* bv = (const float*)d_in[15];
    const float* mv = (const float*)d_in[16];
    const float* vv = (const float*)d_in[17];
    const float* Wq = (const float*)d_in[18];
    const float* Wk = (const float*)d_in[19];
    const float* Wv = (const float*)d_in[20];
    const float* Wo = (const float*)d_in[21];
    const float* bo = (const float*)d_in[22];
    float* out = (float*)d_out;

    float *qin, *kin, *vin, *qh, *vh, *po, *pml;
    uint32_t *kp, *vt;
    cudaGetSymbolAddress((void**)&qin, g_qin);
    cudaGetSymbolAddress((void**)&kin, g_kin);
    cudaGetSymbolAddress((void**)&vin, g_vin);
    cudaGetSymbolAddress((void**)&qh,  g_q);
    cudaGetSymbolAddress((void**)&vh,  g_v);
    cudaGetSymbolAddress((void**)&kp,  g_kp);
    cudaGetSymbolAddress((void**)&vt,  g_vt);
    cudaGetSymbolAddress((void**)&po,  g_po);
    cudaGetSymbolAddress((void**)&pml, g_pml);

    prep_kernel<<<(M_*C_ + 255)/256, 256>>>(x, kq, kk, kv,
                                            gq, bq, mq, vq,
                                            gk, bk, mk, vk,
                                            gv, bv, mv, vv);

    cudaFuncSetAttribute(gemm_qkv, cudaFuncAttributeMaxDynamicSharedMemorySize, GEMM_SMEM_BYTES);
    cudaFuncSetAttribute(gemm_o,   cudaFuncAttributeMaxDynamicSharedMemorySize, GEMM_SMEM_BYTES);

    dim3 gq3((M_ + 127)/128, C_/64, 3);
    gemm_qkv<<<gq3, 256, GEMM_SMEM_BYTES>>>(qin, kin, vin, Wq, Wk, Wv, qh, vh, kp);

    vpack<<<dim3(NKT, DH/32, BH_), 256>>>(vh, vt);

    cudaFuncSetAttribute(attn_tc2,
                         cudaFuncAttributeMaxDynamicSharedMemorySize, ATTN_SMEM);
    attn_tc2<<<dim3((T_ + QB - 1)/QB, BH_, 3), 256, ATTN_SMEM>>>(qh, kp, vt, po, pml);

    gemm_o<<<dim3((M_ + 127)/128, C_/64), 256, GEMM_SMEM_BYTES>>>(po, pml, Wo, bo, out);
}